// round 2
// baseline (speedup 1.0000x reference)
#include <cuda_runtime.h>
#include <math.h>

// Problem constants
#define NPART   65536
#define NSTEPS  50
#define HD      128     // hidden width
#define CTXD    128     // context dim
#define TED     32      // time embedding dim
#define THREADS 256
#define P_CTA   32      // particles per CTA
#define P_WARP  4       // particles per warp
#define NWARP   8
#define H1PAD   132     // padded row length for h1 transposed buffers (multiple of 4)

struct Smem {
    float wA[HD * HD];                       // W1ctx then W2        (64 KB)
    float wB[HD * HD];                       // V1ctx then V2        (64 KB)
    float pc1[P_CTA * HD];                   // ctx@W1ctx + b1       (16 KB) (emb scratch early)
    float cc1[P_CTA * HD];                   // ctx@V1ctx + c1       (16 KB)
    float h1T[NWARP][2][P_WARP * H1PAD];     // per-warp h1 for both nets (33 KB) (W1temb scratch early)
    float te_all[NSTEPS * HD];               // temb(t) @ W1temb     (25.6 KB)
    float w1z[2 * HD];                       // W1 rows 0,1
    float v1z[2 * HD];                       // V1 rows 0,1
    float v1t[HD];                           // V1 row 130 (time column)
    float zbuf[P_CTA * 2];
    float times_s[NSTEPS + 1];
    float dts[NSTEPS];
    float ss[NSTEPS];                        // noise scale per step
};

// Dual register-blocked matvec: acc[p][q] += h[p][k] * W[k][4*lane+q] for both nets.
__device__ __forceinline__ void matvec_dual(
    const float* __restrict__ hTa, const float* __restrict__ hTb,
    const float* __restrict__ wA,  const float* __restrict__ wB,
    int lane, float (&accA)[P_WARP][4], float (&accB)[P_WARP][4])
{
#pragma unroll
    for (int p = 0; p < P_WARP; p++)
#pragma unroll
        for (int q = 0; q < 4; q++) { accA[p][q] = 0.f; accB[p][q] = 0.f; }

#pragma unroll 4
    for (int k = 0; k < HD; k++) {
        float4 wa = *(const float4*)&wA[k * HD + 4 * lane];  // conflict-free LDS.128
        float4 wb = *(const float4*)&wB[k * HD + 4 * lane];
#pragma unroll
        for (int p = 0; p < P_WARP; p++) {
            float ha = hTa[p * H1PAD + k];   // warp-uniform broadcast LDS
            float hb = hTb[p * H1PAD + k];
            accA[p][0] = fmaf(ha, wa.x, accA[p][0]);
            accA[p][1] = fmaf(ha, wa.y, accA[p][1]);
            accA[p][2] = fmaf(ha, wa.z, accA[p][2]);
            accA[p][3] = fmaf(ha, wa.w, accA[p][3]);
            accB[p][0] = fmaf(hb, wb.x, accB[p][0]);
            accB[p][1] = fmaf(hb, wb.y, accB[p][1]);
            accB[p][2] = fmaf(hb, wb.z, accB[p][2]);
            accB[p][3] = fmaf(hb, wb.w, accB[p][3]);
        }
    }
}

__global__ void __launch_bounds__(THREADS, 1)
sde_kernel(const float* __restrict__ z0,
           const float* __restrict__ pctx,
           const float* __restrict__ cctx,
           const float* __restrict__ times,
           const float* __restrict__ xi,
           const float* __restrict__ freqs,
           const float* __restrict__ log_diff,
           const float* __restrict__ W1, const float* __restrict__ b1,
           const float* __restrict__ W2, const float* __restrict__ b2,
           const float* __restrict__ W3, const float* __restrict__ b3,
           const float* __restrict__ V1, const float* __restrict__ c1,
           const float* __restrict__ V2, const float* __restrict__ c2,
           const float* __restrict__ V3, const float* __restrict__ c3,
           float* __restrict__ traj)
{
    extern __shared__ float smraw[];
    Smem* sm = reinterpret_cast<Smem*>(smraw);

    const int tid   = threadIdx.x;
    const int wid   = tid >> 5;
    const int lane  = tid & 31;
    const int p0    = lane >> 3;   // this lane's particle (layer-1 work split)
    const int kg    = lane & 7;    // this lane's k-group (16 k values)
    const int nBase = blockIdx.x * P_CTA;
    const int nWarp = nBase + wid * P_WARP;

    // ---------------- prologue ----------------
    for (int i = tid; i <= NSTEPS; i += THREADS) sm->times_s[i] = times[i];
    float gb = log1pf(expf(log_diff[0]));   // softplus
    __syncthreads();
    if (tid < NSTEPS) {
        float t_i = sm->times_s[tid];
        float dt  = sm->times_s[tid + 1] - t_i;
        sm->dts[tid] = dt;
        sm->ss[tid]  = gb * (1.f - t_i) * sqrtf(fmaxf(dt, 1e-12f));
    }

    // W1temb rows (130..161) -> scratch in h1T region; emb table -> scratch in pc1 region
    float* wtmp = &sm->h1T[0][0][0];          // 4096 floats needed, region has 4224/warp*... plenty
    for (int i = tid; i < TED * HD; i += THREADS) wtmp[i] = W1[130 * HD + i];
    float* emb = sm->pc1;                     // NSTEPS*TED = 1600 floats
    for (int e = tid; e < NSTEPS * TED; e += THREADS) {
        int t = e / TED, i = e % TED;
        float arg = 6.2831853071795864769f * times[t] * freqs[i & 15];
        emb[e] = (i < 16) ? sinf(arg) : cosf(arg);
    }
    __syncthreads();

    // te_all[t][j] = emb(t) @ W1temb
    for (int e = tid; e < NSTEPS * HD; e += THREADS) {
        int t = e / HD, j = e % HD;
        float a = 0.f;
#pragma unroll
        for (int m = 0; m < TED; m++) a = fmaf(emb[t * TED + m], wtmp[m * HD + j], a);
        sm->te_all[e] = a;
    }
    __syncthreads();   // done with emb + wtmp scratch

    // ctx weight blocks: W1 rows 2..129 -> wA, V1 rows 2..129 -> wB
    for (int i = tid * 4; i < HD * HD; i += THREADS * 4) {
        *(float4*)&sm->wA[i] = *(const float4*)&W1[2 * HD + i];
        *(float4*)&sm->wB[i] = *(const float4*)&V1[2 * HD + i];
    }
    __syncthreads();

    // ---- one-time ctx projections: pc1 = pctx@W1ctx + b1, cc1 = cctx@V1ctx + c1 ----
    {
        float* hTa = sm->h1T[wid][0];
        float* hTb = sm->h1T[wid][1];
        const float* srcp = pctx + (size_t)nWarp * CTXD;
        const float* srcc = cctx + (size_t)nWarp * CTXD;
#pragma unroll
        for (int j = 0; j < 4; j++) {
            int k = kg * 16 + 4 * j;
            *(float4*)&hTa[p0 * H1PAD + k] = *(const float4*)&srcp[p0 * CTXD + k];
            *(float4*)&hTb[p0 * H1PAD + k] = *(const float4*)&srcc[p0 * CTXD + k];
        }
        __syncwarp();
        float accA[P_WARP][4], accB[P_WARP][4];
        matvec_dual(hTa, hTb, sm->wA, sm->wB, lane, accA, accB);
        float4 b1v = *(const float4*)&b1[4 * lane];
        float4 c1v = *(const float4*)&c1[4 * lane];
#pragma unroll
        for (int p = 0; p < P_WARP; p++) {
            float4 oa, ob;
            oa.x = accA[p][0] + b1v.x; oa.y = accA[p][1] + b1v.y;
            oa.z = accA[p][2] + b1v.z; oa.w = accA[p][3] + b1v.w;
            ob.x = accB[p][0] + c1v.x; ob.y = accB[p][1] + c1v.y;
            ob.z = accB[p][2] + c1v.z; ob.w = accB[p][3] + c1v.w;
            *(float4*)&sm->pc1[(wid * P_WARP + p) * HD + 4 * lane] = oa;
            *(float4*)&sm->cc1[(wid * P_WARP + p) * HD + 4 * lane] = ob;
        }
    }
    __syncthreads();   // everyone done reading wA/wB

    // step weights: W2 -> wA, V2 -> wB; small params
    for (int i = tid * 4; i < HD * HD; i += THREADS * 4) {
        *(float4*)&sm->wA[i] = *(const float4*)&W2[i];
        *(float4*)&sm->wB[i] = *(const float4*)&V2[i];
    }
    for (int i = tid; i < HD; i += THREADS) {
        sm->w1z[i]      = W1[i];
        sm->w1z[HD + i] = W1[HD + i];
        sm->v1z[i]      = V1[i];
        sm->v1z[HD + i] = V1[HD + i];
        sm->v1t[i]      = V1[130 * HD + i];
    }
    for (int i = tid; i < P_CTA * 2; i += THREADS) {
        float v = z0[(size_t)nBase * 2 + i];
        sm->zbuf[i] = v;
        traj[(size_t)nBase * 2 + i] = v;      // traj[0] = z0
    }

    // per-lane epilogue constants (registers, held across all steps)
    float4 b2v = *(const float4*)&b2[4 * lane];
    float4 c2v = *(const float4*)&c2[4 * lane];
    float b2a[4] = {b2v.x, b2v.y, b2v.z, b2v.w};
    float c2a[4] = {c2v.x, c2v.y, c2v.z, c2v.w};
    float w30[4], w31[4], v30[4], v31[4];
#pragma unroll
    for (int q = 0; q < 4; q++) {
        w30[q] = W3[(4 * lane + q) * 2 + 0];
        w31[q] = W3[(4 * lane + q) * 2 + 1];
        v30[q] = V3[(4 * lane + q) * 2 + 0];
        v31[q] = V3[(4 * lane + q) * 2 + 1];
    }
    float bc0 = (lane == 0) ? (b3[0] + c3[0]) : 0.f;
    float bc1 = (lane == 0) ? (b3[1] + c3[1]) : 0.f;
    __syncthreads();

    // ---------------- time-step loop (warp-synchronous only) ----------------
    float* hTa = sm->h1T[wid][0];
    float* hTb = sm->h1T[wid][1];
    const float* pcrow = &sm->pc1[(wid * P_WARP + p0) * HD];
    const float* ccrow = &sm->cc1[(wid * P_WARP + p0) * HD];

    for (int t = 0; t < NSTEPS; t++) {
        float t_i = sm->times_s[t];
        float dt  = sm->dts[t];
        float s   = sm->ss[t];
        float zp0 = sm->zbuf[(wid * P_WARP + p0) * 2 + 0];
        float zp1 = sm->zbuf[(wid * P_WARP + p0) * 2 + 1];

        // layer 1, both nets: h1 = relu(pc1 + z·W1z + te[t]) ; g1 = tanh(cc1 + z·V1z + t·V1t)
#pragma unroll
        for (int j = 0; j < 4; j++) {
            int k = kg * 16 + 4 * j;
            float4 pc = *(const float4*)&pcrow[k];
            float4 w0 = *(const float4*)&sm->w1z[k];
            float4 w1 = *(const float4*)&sm->w1z[HD + k];
            float4 te = *(const float4*)&sm->te_all[t * HD + k];
            float4 oa;
            oa.x = fmaxf(fmaf(zp1, w1.x, fmaf(zp0, w0.x, pc.x + te.x)), 0.f);
            oa.y = fmaxf(fmaf(zp1, w1.y, fmaf(zp0, w0.y, pc.y + te.y)), 0.f);
            oa.z = fmaxf(fmaf(zp1, w1.z, fmaf(zp0, w0.z, pc.z + te.z)), 0.f);
            oa.w = fmaxf(fmaf(zp1, w1.w, fmaf(zp0, w0.w, pc.w + te.w)), 0.f);
            *(float4*)&hTa[p0 * H1PAD + k] = oa;

            float4 cc = *(const float4*)&ccrow[k];
            float4 u0 = *(const float4*)&sm->v1z[k];
            float4 u1 = *(const float4*)&sm->v1z[HD + k];
            float4 vt = *(const float4*)&sm->v1t[k];
            float4 ob;
            ob.x = tanhf(fmaf(zp1, u1.x, fmaf(zp0, u0.x, fmaf(t_i, vt.x, cc.x))));
            ob.y = tanhf(fmaf(zp1, u1.y, fmaf(zp0, u0.y, fmaf(t_i, vt.y, cc.y))));
            ob.z = tanhf(fmaf(zp1, u1.z, fmaf(zp0, u0.z, fmaf(t_i, vt.z, cc.z))));
            ob.w = tanhf(fmaf(zp1, u1.w, fmaf(zp0, u0.w, fmaf(t_i, vt.w, cc.w))));
            *(float4*)&hTb[p0 * H1PAD + k] = ob;
        }
        __syncwarp();

        // layer 2 (both nets), fused layer-3 projection in epilogue
        float accA[P_WARP][4], accB[P_WARP][4];
        matvec_dual(hTa, hTb, sm->wA, sm->wB, lane, accA, accB);

        float d0[P_WARP], d1[P_WARP];
#pragma unroll
        for (int p = 0; p < P_WARP; p++) {
            float a0 = bc0, a1 = bc1;
#pragma unroll
            for (int q = 0; q < 4; q++) {
                float h2 = fmaxf(accA[p][q] + b2a[q], 0.f);
                a0 = fmaf(h2, w30[q], a0);
                a1 = fmaf(h2, w31[q], a1);
                float g2 = tanhf(accB[p][q] + c2a[q]);
                a0 = fmaf(g2, v30[q], a0);
                a1 = fmaf(g2, v31[q], a1);
            }
            d0[p] = a0; d1[p] = a1;
        }
        // warp reduce the 8 drift partials
#pragma unroll
        for (int off = 16; off > 0; off >>= 1) {
#pragma unroll
            for (int p = 0; p < P_WARP; p++) {
                d0[p] += __shfl_xor_sync(0xffffffffu, d0[p], off);
                d1[p] += __shfl_xor_sync(0xffffffffu, d1[p], off);
            }
        }

        // Euler + Euler-Maruyama update (lanes 0..3 own one particle each)
        if (lane < P_WARP) {
            int p = lane;
            int n = nWarp + p;
            float dd0 = (p == 0) ? d0[0] : (p == 1) ? d0[1] : (p == 2) ? d0[2] : d0[3];
            float dd1 = (p == 0) ? d1[0] : (p == 1) ? d1[1] : (p == 2) ? d1[2] : d1[3];
            float zz0 = sm->zbuf[(wid * P_WARP + p) * 2 + 0];
            float zz1 = sm->zbuf[(wid * P_WARP + p) * 2 + 1];
            float2 xv = *(const float2*)&xi[((size_t)t * NPART + n) * 2];
            float zn0 = fmaf(dd0, dt, zz0) + xv.x * s;
            float zn1 = fmaf(dd1, dt, zz1) + xv.y * s;
            sm->zbuf[(wid * P_WARP + p) * 2 + 0] = zn0;
            sm->zbuf[(wid * P_WARP + p) * 2 + 1] = zn1;
            *(float2*)&traj[((size_t)(t + 1) * NPART + n) * 2] = make_float2(zn0, zn1);
        }
        __syncwarp();
    }
}

extern "C" void kernel_launch(void* const* d_in, const int* in_sizes, int n_in,
                              void* d_out, int out_size)
{
    (void)in_sizes; (void)n_in; (void)out_size;
    const float* z0       = (const float*)d_in[0];
    const float* pctx     = (const float*)d_in[1];
    const float* cctx     = (const float*)d_in[2];
    const float* times    = (const float*)d_in[3];
    const float* xi       = (const float*)d_in[4];
    const float* freqs    = (const float*)d_in[5];
    const float* log_diff = (const float*)d_in[6];
    const float* W1 = (const float*)d_in[7];
    const float* b1 = (const float*)d_in[8];
    const float* W2 = (const float*)d_in[9];
    const float* b2 = (const float*)d_in[10];
    const float* W3 = (const float*)d_in[11];
    const float* b3 = (const float*)d_in[12];
    const float* V1 = (const float*)d_in[13];
    const float* c1 = (const float*)d_in[14];
    const float* V2 = (const float*)d_in[15];
    const float* c2 = (const float*)d_in[16];
    const float* V3 = (const float*)d_in[17];
    const float* c3 = (const float*)d_in[18];
    float* traj = (float*)d_out;

    cudaFuncSetAttribute(sde_kernel, cudaFuncAttributeMaxDynamicSharedMemorySize,
                         (int)sizeof(Smem));
    sde_kernel<<<NPART / P_CTA, THREADS, sizeof(Smem)>>>(
        z0, pctx, cctx, times, xi, freqs, log_diff,
        W1, b1, W2, b2, W3, b3, V1, c1, V2, c2, V3, c3, traj);
}

// round 4
// speedup vs baseline: 1.6710x; 1.6710x over previous
#include <cuda_runtime.h>
#include <cuda_bf16.h>
#include <mma.h>
#include <math.h>
#include <stdint.h>

using namespace nvcuda;

#define NPART   65536
#define NSTEPS  50
#define HD      128
#define LDA     136      // padded bf16 row length (multiple of 8 elems = 16B)
#define THREADS 256
#define P_CTA   128
#define GRID    (NPART / P_CTA)

__device__ float g_te[NSTEPS * HD];   // b1 + emb(t) @ W1[130:162]

struct Smem {
    __nv_bfloat16 A[2][P_CTA * LDA];      // [hi/lo] activations        69632 B
    __nv_bfloat16 B[2][2][HD * LDA];      // [net][hi/lo] weights      139264 B
    float scr[8][16 * 16];                // per-warp epilogue scratch   8192 B
    float w1z[2 * HD], v1z[2 * HD], v1t[HD];
    float b2s[HD], c2s[HD];
    float w3s[2 * HD], v3s[2 * HD];
    float times_s[NSTEPS + 1], dts[NSTEPS], ss[NSTEPS];
};

__device__ __forceinline__ float tanhf_fast(float x) {
    float e = __expf(2.0f * x);
    return 1.0f - __fdividef(2.0f, e + 1.0f);
}

// fp32 -> (hi, lo) bf16 split, 64 values -> A tiles at row p, cols j0..j0+63
__device__ __forceinline__ void store_split64(Smem* sm, int p, int j0, const float* v) {
#pragma unroll
    for (int c = 0; c < 8; c++) {
        uint32_t uh[4], ul[4];
#pragma unroll
        for (int e = 0; e < 4; e++) {
            float a = v[c * 8 + 2 * e], b = v[c * 8 + 2 * e + 1];
            __nv_bfloat162 th, tl;
            th.x = __float2bfloat16(a);
            th.y = __float2bfloat16(b);
            tl.x = __float2bfloat16(a - __bfloat162float(th.x));
            tl.y = __float2bfloat16(b - __bfloat162float(th.y));
            uh[e] = *(uint32_t*)&th;
            ul[e] = *(uint32_t*)&tl;
        }
        int off = p * LDA + j0 + c * 8;
        *(uint4*)&sm->A[0][off] = make_uint4(uh[0], uh[1], uh[2], uh[3]);
        *(uint4*)&sm->A[1][off] = make_uint4(ul[0], ul[1], ul[2], ul[3]);
    }
}

// weight [128][128] row-major -> hi/lo bf16 tiles with LDA padding
__device__ __forceinline__ void fill_wsplit(const float* __restrict__ src,
                                            __nv_bfloat16* hi, __nv_bfloat16* lo, int tid) {
    for (int idx = tid; idx < HD * HD; idx += THREADS) {
        int k = idx >> 7, n = idx & 127;
        float x = src[idx];
        __nv_bfloat16 h = __float2bfloat16(x);
        float l = x - __bfloat162float(h);
        hi[k * LDA + n] = h;
        lo[k * LDA + n] = __float2bfloat16(l);
    }
}

// MODE 0: raw D -> out64 (ctx prologue). MODE 1: relu epilogue. MODE 2: tanh epilogue.
template<int MODE>
__device__ __forceinline__ void run_gemm(Smem* sm,
    const __nv_bfloat16* __restrict__ Bhi, const __nv_bfloat16* __restrict__ Blo,
    float* scrw, int w, int lane,
    const float* __restrict__ bias, const float* __restrict__ w3arr,
    float* out64, float& d0, float& d1)
{
    wmma::fragment<wmma::matrix_a, 16, 16, 16, __nv_bfloat16, wmma::row_major> ahi[8], alo[8];
    const __nv_bfloat16* Ahi = sm->A[0] + w * 16 * LDA;
    const __nv_bfloat16* Alo = sm->A[1] + w * 16 * LDA;
#pragma unroll
    for (int k = 0; k < 8; k++) {
        wmma::load_matrix_sync(ahi[k], Ahi + k * 16, LDA);
        wmma::load_matrix_sync(alo[k], Alo + k * 16, LDA);
    }
    const int r  = lane >> 1;
    const int cb = (lane & 1) * 8;

#pragma unroll
    for (int nt = 0; nt < 8; nt++) {
        wmma::fragment<wmma::accumulator, 16, 16, 16, float> acc0, acc1;
        wmma::fill_fragment(acc0, 0.0f);
        wmma::fill_fragment(acc1, 0.0f);
#pragma unroll
        for (int k = 0; k < 8; k += 2) {
            wmma::fragment<wmma::matrix_b, 16, 16, 16, __nv_bfloat16, wmma::row_major> bh, bl;
            wmma::load_matrix_sync(bh, Bhi + k * 16 * LDA + nt * 16, LDA);
            wmma::mma_sync(acc0, ahi[k], bh, acc0);
            wmma::mma_sync(acc0, alo[k], bh, acc0);
            wmma::load_matrix_sync(bl, Blo + k * 16 * LDA + nt * 16, LDA);
            wmma::mma_sync(acc0, ahi[k], bl, acc0);
            wmma::load_matrix_sync(bh, Bhi + (k + 1) * 16 * LDA + nt * 16, LDA);
            wmma::mma_sync(acc1, ahi[k + 1], bh, acc1);
            wmma::mma_sync(acc1, alo[k + 1], bh, acc1);
            wmma::load_matrix_sync(bl, Blo + (k + 1) * 16 * LDA + nt * 16, LDA);
            wmma::mma_sync(acc1, ahi[k + 1], bl, acc1);
        }
#pragma unroll
        for (int i = 0; i < acc0.num_elements; i++) acc0.x[i] += acc1.x[i];
        wmma::store_matrix_sync(scrw, acc0, 16, wmma::mem_row_major);
        __syncwarp();

        if (MODE == 0) {
            if ((lane & 1) == (nt >> 2)) {
#pragma unroll
                for (int i = 0; i < 16; i++) out64[(nt & 3) * 16 + i] = scrw[r * 16 + i];
            }
        } else {
            const float* row = &scrw[r * 16 + cb];
#pragma unroll
            for (int i = 0; i < 8; i++) {
                int n = nt * 16 + cb + i;
                float x = row[i] + bias[n];
                float a = (MODE == 1) ? fmaxf(x, 0.0f) : tanhf_fast(x);
                float2 w3 = *(const float2*)&w3arr[2 * n];
                d0 = fmaf(a, w3.x, d0);
                d1 = fmaf(a, w3.y, d1);
            }
        }
        __syncwarp();
    }
}

// tiny pre-kernel: g_te[t][j] = b1[j] + sum_m emb(t,m) * W1[(130+m)*128 + j]
__global__ void te_kernel(const float* __restrict__ times, const float* __restrict__ freqs,
                          const float* __restrict__ W1, const float* __restrict__ b1)
{
    __shared__ float emb[NSTEPS * 32];
    int tid = threadIdx.x;
    for (int e = tid; e < NSTEPS * 32; e += blockDim.x) {
        int t = e >> 5, i = e & 31;
        float arg = 6.2831853071795864769f * times[t] * freqs[i & 15];
        emb[e] = (i < 16) ? sinf(arg) : cosf(arg);
    }
    __syncthreads();
    for (int e = tid; e < NSTEPS * HD; e += blockDim.x) {
        int t = e >> 7, j = e & 127;
        float a = b1[j];
#pragma unroll
        for (int m = 0; m < 32; m++) a = fmaf(emb[t * 32 + m], W1[(130 + m) * HD + j], a);
        g_te[e] = a;
    }
}

__global__ void __launch_bounds__(THREADS, 1)
sde_kernel(const float* __restrict__ z0, const float* __restrict__ pctx,
           const float* __restrict__ cctx, const float* __restrict__ times,
           const float* __restrict__ xi, const float* __restrict__ freqs,
           const float* __restrict__ log_diff,
           const float* __restrict__ W1, const float* __restrict__ b1,
           const float* __restrict__ W2, const float* __restrict__ b2,
           const float* __restrict__ W3, const float* __restrict__ b3,
           const float* __restrict__ V1, const float* __restrict__ c1,
           const float* __restrict__ V2, const float* __restrict__ c2,
           const float* __restrict__ V3, const float* __restrict__ c3,
           float* __restrict__ traj)
{
    extern __shared__ char raw[];
    Smem* sm = (Smem*)raw;

    const int tid   = threadIdx.x;
    const int wid   = tid >> 5;
    const int lane  = tid & 31;
    const int p     = wid * 16 + (lane >> 1);   // this thread's particle
    const int j0    = (lane & 1) * 64;          // this thread's column range
    const int nBase = blockIdx.x * P_CTA;
    float* scrw = &sm->scr[wid][0];

    // ---- tables & params ----
    for (int i = tid; i <= NSTEPS; i += THREADS) sm->times_s[i] = times[i];
    float gb = log1pf(expf(log_diff[0]));
    for (int i = tid; i < 2 * HD; i += THREADS) {
        sm->w1z[i] = W1[i];
        sm->v1z[i] = V1[i];
        sm->w3s[i] = W3[i];
        sm->v3s[i] = V3[i];
    }
    for (int i = tid; i < HD; i += THREADS) {
        sm->v1t[i] = V1[130 * HD + i];
        sm->b2s[i] = b2[i];
        sm->c2s[i] = c2[i];
    }
    // prologue weights: W1ctx -> B[0], V1ctx -> B[1]
    fill_wsplit(W1 + 2 * HD, sm->B[0][0], sm->B[0][1], tid);
    fill_wsplit(V1 + 2 * HD, sm->B[1][0], sm->B[1][1], tid);
    __syncthreads();
    if (tid < NSTEPS) {
        float t_i = sm->times_s[tid];
        float dt  = sm->times_s[tid + 1] - t_i;
        sm->dts[tid] = dt;
        sm->ss[tid]  = gb * (1.0f - t_i) * sqrtf(fmaxf(dt, 1e-12f));
    }

    // ---- prologue GEMM 1: pc1 = pctx @ W1ctx ----
    {
        float v[64];
        const float* src = pctx + (size_t)(nBase + p) * HD + j0;
#pragma unroll
        for (int c = 0; c < 16; c++) {
            float4 q = *(const float4*)&src[4 * c];
            v[4 * c] = q.x; v[4 * c + 1] = q.y; v[4 * c + 2] = q.z; v[4 * c + 3] = q.w;
        }
        store_split64(sm, p, j0, v);
    }
    __syncthreads();
    float pc1r[64], cc1r[64];
    float dum0 = 0.f, dum1 = 0.f;
    run_gemm<0>(sm, sm->B[0][0], sm->B[0][1], scrw, wid, lane, nullptr, nullptr, pc1r, dum0, dum1);
    __syncthreads();

    // ---- prologue GEMM 2: cc1 = cctx @ V1ctx + c1 ----
    {
        float v[64];
        const float* src = cctx + (size_t)(nBase + p) * HD + j0;
#pragma unroll
        for (int c = 0; c < 16; c++) {
            float4 q = *(const float4*)&src[4 * c];
            v[4 * c] = q.x; v[4 * c + 1] = q.y; v[4 * c + 2] = q.z; v[4 * c + 3] = q.w;
        }
        store_split64(sm, p, j0, v);
    }
    __syncthreads();
    run_gemm<0>(sm, sm->B[1][0], sm->B[1][1], scrw, wid, lane, nullptr, nullptr, cc1r, dum0, dum1);
    __syncthreads();
#pragma unroll
    for (int i = 0; i < 64; i++) cc1r[i] += __ldg(&c1[j0 + i]);

    // ---- step weights: W2 -> B[0], V2 -> B[1] ----
    fill_wsplit(W2, sm->B[0][0], sm->B[0][1], tid);
    fill_wsplit(V2, sm->B[1][0], sm->B[1][1], tid);

    float2 z = *(const float2*)&z0[(size_t)(nBase + p) * 2];
    if ((lane & 1) == 0) *(float2*)&traj[(size_t)(nBase + p) * 2] = z;
    const float bc0 = b3[0] + c3[0];
    const float bc1 = b3[1] + c3[1];
    __syncthreads();

    // ---------------- time loop ----------------
    for (int t = 0; t < NSTEPS; t++) {
        const float t_i = sm->times_s[t];
        const float dt  = sm->dts[t];
        const float s   = sm->ss[t];

        // build h1A = relu(pc1 + z.W1z + te[t])
        {
            float v[64];
#pragma unroll
            for (int c = 0; c < 16; c++) {
                int j = j0 + 4 * c;
                float4 te = __ldg((const float4*)&g_te[t * HD + j]);
                float4 w0 = *(const float4*)&sm->w1z[j];
                float4 w1 = *(const float4*)&sm->w1z[HD + j];
                v[4*c]   = fmaxf(fmaf(z.y, w1.x, fmaf(z.x, w0.x, pc1r[4*c]   + te.x)), 0.f);
                v[4*c+1] = fmaxf(fmaf(z.y, w1.y, fmaf(z.x, w0.y, pc1r[4*c+1] + te.y)), 0.f);
                v[4*c+2] = fmaxf(fmaf(z.y, w1.z, fmaf(z.x, w0.z, pc1r[4*c+2] + te.z)), 0.f);
                v[4*c+3] = fmaxf(fmaf(z.y, w1.w, fmaf(z.x, w0.w, pc1r[4*c+3] + te.w)), 0.f);
            }
            store_split64(sm, p, j0, v);
        }
        __syncthreads();

        float d0 = 0.f, d1 = 0.f;
        run_gemm<1>(sm, sm->B[0][0], sm->B[0][1], scrw, wid, lane, sm->b2s, sm->w3s, nullptr, d0, d1);
        __syncthreads();

        // build h1B = tanh(cc1 + z.V1z + t*V1t)
        {
            float v[64];
#pragma unroll
            for (int c = 0; c < 16; c++) {
                int j = j0 + 4 * c;
                float4 u0 = *(const float4*)&sm->v1z[j];
                float4 u1 = *(const float4*)&sm->v1z[HD + j];
                float4 vt = *(const float4*)&sm->v1t[j];
                v[4*c]   = tanhf_fast(fmaf(z.y, u1.x, fmaf(z.x, u0.x, fmaf(t_i, vt.x, cc1r[4*c]))));
                v[4*c+1] = tanhf_fast(fmaf(z.y, u1.y, fmaf(z.x, u0.y, fmaf(t_i, vt.y, cc1r[4*c+1]))));
                v[4*c+2] = tanhf_fast(fmaf(z.y, u1.z, fmaf(z.x, u0.z, fmaf(t_i, vt.z, cc1r[4*c+2]))));
                v[4*c+3] = tanhf_fast(fmaf(z.y, u1.w, fmaf(z.x, u0.w, fmaf(t_i, vt.w, cc1r[4*c+3]))));
            }
            store_split64(sm, p, j0, v);
        }
        __syncthreads();

        run_gemm<2>(sm, sm->B[1][0], sm->B[1][1], scrw, wid, lane, sm->c2s, sm->v3s, nullptr, d0, d1);

        // combine lane pair (two n-halves of the same particle), update z
        d0 += __shfl_xor_sync(0xffffffffu, d0, 1);
        d1 += __shfl_xor_sync(0xffffffffu, d1, 1);
        float2 xv = *(const float2*)&xi[((size_t)t * NPART + nBase + p) * 2];
        z.x = fmaf(d0 + bc0, dt, z.x) + xv.x * s;
        z.y = fmaf(d1 + bc1, dt, z.y) + xv.y * s;
        if ((lane & 1) == 0)
            *(float2*)&traj[((size_t)(t + 1) * NPART + nBase + p) * 2] = z;
        __syncthreads();
    }
}

extern "C" void kernel_launch(void* const* d_in, const int* in_sizes, int n_in,
                              void* d_out, int out_size)
{
    (void)in_sizes; (void)n_in; (void)out_size;
    const float* z0       = (const float*)d_in[0];
    const float* pctx     = (const float*)d_in[1];
    const float* cctx     = (const float*)d_in[2];
    const float* times    = (const float*)d_in[3];
    const float* xi       = (const float*)d_in[4];
    const float* freqs    = (const float*)d_in[5];
    const float* log_diff = (const float*)d_in[6];
    const float* W1 = (const float*)d_in[7];
    const float* b1 = (const float*)d_in[8];
    const float* W2 = (const float*)d_in[9];
    const float* b2 = (const float*)d_in[10];
    const float* W3 = (const float*)d_in[11];
    const float* b3 = (const float*)d_in[12];
    const float* V1 = (const float*)d_in[13];
    const float* c1 = (const float*)d_in[14];
    const float* V2 = (const float*)d_in[15];
    const float* c2 = (const float*)d_in[16];
    const float* V3 = (const float*)d_in[17];
    const float* c3 = (const float*)d_in[18];
    float* traj = (float*)d_out;

    te_kernel<<<1, 512>>>(times, freqs, W1, b1);

    cudaFuncSetAttribute(sde_kernel, cudaFuncAttributeMaxDynamicSharedMemorySize,
                         (int)sizeof(Smem));
    sde_kernel<<<GRID, THREADS, sizeof(Smem)>>>(
        z0, pctx, cctx, times, xi, freqs, log_diff,
        W1, b1, W2, b2, W3, b3, V1, c1, V2, c2, V3, c3, traj);
}